// round 15
// baseline (speedup 1.0000x reference)
#include <cuda_runtime.h>
#include <cuda_bf16.h>
#include <math.h>

#define TT   4096
#define HIDN 4096
#define HH   32
#define DD   64
#define PP   2048

typedef __nv_bfloat16 bf16;

// ---------------- scratch (16B-aligned: 16-byte vector/cp.async access) --------
__device__ __align__(16) float d_qpre[(size_t)TT * PP];
__device__ __align__(16) float d_kpre[(size_t)TT * PP];
__device__ __align__(16) float d_vpre[(size_t)TT * PP];
__device__ __align__(16) float d_qn[(size_t)TT * PP];
__device__ __align__(16) float d_kn[(size_t)TT * PP];
__device__ __align__(16) float d_vn[(size_t)TT * PP];
__device__ __align__(16) float d_g[(size_t)TT * PP];
__device__ __align__(16) float d_g2[(size_t)TT * PP];
__device__ __align__(16) float d_ob[(size_t)TT * PP];
__device__ __align__(16) float d_beta[(size_t)TT * HH];
__device__ __align__(16) float d_fa[(size_t)TT * DD];
__device__ __align__(16) float d_ga[(size_t)TT * DD];
// bf16 split operands
__device__ __align__(16) bf16 d_xh[(size_t)TT * HIDN];
__device__ __align__(16) bf16 d_xl[(size_t)TT * HIDN];
__device__ __align__(16) bf16 d_wqth[(size_t)PP * HIDN];
__device__ __align__(16) bf16 d_wqtl[(size_t)PP * HIDN];
__device__ __align__(16) bf16 d_wkth[(size_t)PP * HIDN];
__device__ __align__(16) bf16 d_wktl[(size_t)PP * HIDN];
__device__ __align__(16) bf16 d_wvth[(size_t)PP * HIDN];
__device__ __align__(16) bf16 d_wvtl[(size_t)PP * HIDN];
__device__ __align__(16) bf16 d_woth[(size_t)HIDN * PP];
__device__ __align__(16) bf16 d_wotl[(size_t)HIDN * PP];
__device__ __align__(16) bf16 d_obh[(size_t)TT * PP];
__device__ __align__(16) bf16 d_obl[(size_t)TT * PP];

// ---------------- PTX helpers ----------------
__device__ __forceinline__ void mma16816(float* c, const unsigned* a, const unsigned* b) {
    asm volatile(
        "mma.sync.aligned.m16n8k16.row.col.f32.bf16.bf16.f32 "
        "{%0,%1,%2,%3}, {%4,%5,%6,%7}, {%8,%9}, {%0,%1,%2,%3};\n"
        : "+f"(c[0]), "+f"(c[1]), "+f"(c[2]), "+f"(c[3])
        : "r"(a[0]), "r"(a[1]), "r"(a[2]), "r"(a[3]), "r"(b[0]), "r"(b[1]));
}
__device__ __forceinline__ void ldsm4(unsigned* r, unsigned addr) {
    asm volatile("ldmatrix.sync.aligned.m8n8.x4.shared.b16 {%0,%1,%2,%3}, [%4];"
                 : "=r"(r[0]), "=r"(r[1]), "=r"(r[2]), "=r"(r[3]) : "r"(addr));
}
__device__ __forceinline__ void cpasync16(unsigned s, const void* g) {
    asm volatile("cp.async.cg.shared.global [%0], [%1], 16;" :: "r"(s), "l"(g));
}
__device__ __forceinline__ void cpcommit() { asm volatile("cp.async.commit_group;"); }

// ---------------- tensor-core split-bf16 GEMM -------------------------------
// C[M,N] = A[M,K] @ B[K,N], with A given as (Ah+Al) bf16 row-major [M,K]
// and B given transposed as (Bh+Bl) bf16 [N,K]. M%128==0, N%128==0, K%16==0.
#define ARSTB 6144       // bytes per array per stage (128*24*2)
#define STSTB 24576      // bytes per stage (4 arrays)

__global__ __launch_bounds__(256, 1)
void gemm_tc(const bf16* __restrict__ Ah, const bf16* __restrict__ Al,
             const bf16* __restrict__ Bh, const bf16* __restrict__ Bl,
             float* __restrict__ C, int M, int N, int K) {
    __shared__ __align__(16) bf16 sm[2 * 4 * 128 * 24];   // 49152 bytes
    const unsigned sbase = (unsigned)__cvta_generic_to_shared(sm);
    const int tid = threadIdx.x;
    const int bm = blockIdx.y * 128;
    const int bn = blockIdx.x * 128;
    const int warp = tid >> 5;
    const int l = tid & 31;
    const int wm = warp >> 1;     // 0..3 -> row base wm*32
    const int wn = warp & 1;      // 0..1 -> col base wn*64

    // loader mapping: 256 threads -> 128 rows x 2 halves of 16B
    const int lr = tid >> 1, lh = tid & 1;
    const unsigned ldoff = lr * 48 + lh * 16;
    const bf16* pAh = Ah + (size_t)(bm + lr) * K + lh * 8;
    const bf16* pAl = Al + (size_t)(bm + lr) * K + lh * 8;
    const bf16* pBh = Bh + (size_t)(bn + lr) * K + lh * 8;
    const bf16* pBl = Bl + (size_t)(bn + lr) * K + lh * 8;

    // ldmatrix per-thread byte offsets within a stage+array
    unsigned aoff[2], boff[4];
#pragma unroll
    for (int i = 0; i < 2; i++)
        aoff[i] = (unsigned)(((wm * 32 + i * 16 + (l & 15)) * 24 + (l >> 4) * 8) * 2);
#pragma unroll
    for (int p = 0; p < 4; p++)
        boff[p] = (unsigned)(((wn * 64 + p * 16 + (l & 7) + ((l & 16) ? 8 : 0)) * 24
                              + ((l >> 3) & 1) * 8) * 2);

    float acc[2][8][4];
#pragma unroll
    for (int mi = 0; mi < 2; mi++)
#pragma unroll
        for (int ni = 0; ni < 8; ni++)
#pragma unroll
            for (int j = 0; j < 4; j++) acc[mi][ni][j] = 0.f;

    const int KT = K >> 4;
    // prefetch stage 0
    {
        unsigned base = sbase + ldoff;
        cpasync16(base,             pAh);
        cpasync16(base + ARSTB,     pAl);
        cpasync16(base + 2 * ARSTB, pBh);
        cpasync16(base + 3 * ARSTB, pBl);
        cpcommit();
    }
    for (int kt = 0; kt < KT; kt++) {
        if (kt + 1 < KT) {
            const int k0 = (kt + 1) << 4;
            unsigned base = sbase + ((kt + 1) & 1) * STSTB + ldoff;
            cpasync16(base,             pAh + k0);
            cpasync16(base + ARSTB,     pAl + k0);
            cpasync16(base + 2 * ARSTB, pBh + k0);
            cpasync16(base + 3 * ARSTB, pBl + k0);
            cpcommit();
            asm volatile("cp.async.wait_group 1;");
        } else {
            asm volatile("cp.async.wait_group 0;");
        }
        __syncthreads();
        const unsigned stb = sbase + (kt & 1) * STSTB;
        unsigned af[2][2][4];   // [arr][tile][4]
        unsigned bb[2][4][4];   // [arr][pair][4]
#pragma unroll
        for (int arr = 0; arr < 2; arr++)
#pragma unroll
            for (int i = 0; i < 2; i++)
                ldsm4(af[arr][i], stb + arr * ARSTB + aoff[i]);
#pragma unroll
        for (int arr = 0; arr < 2; arr++)
#pragma unroll
            for (int p = 0; p < 4; p++)
                ldsm4(bb[arr][p], stb + (2 + arr) * ARSTB + boff[p]);
#pragma unroll
        for (int mi = 0; mi < 2; mi++)
#pragma unroll
            for (int ni = 0; ni < 8; ni++) {
                const int p = ni >> 1;
                const unsigned* bh = &bb[0][p][(ni & 1) * 2];
                const unsigned* bl = &bb[1][p][(ni & 1) * 2];
                mma16816(acc[mi][ni], af[0][mi], bh);
                mma16816(acc[mi][ni], af[0][mi], bl);
                mma16816(acc[mi][ni], af[1][mi], bh);
            }
        __syncthreads();
    }
    // epilogue
#pragma unroll
    for (int mi = 0; mi < 2; mi++)
#pragma unroll
        for (int ni = 0; ni < 8; ni++) {
            const int row = bm + wm * 32 + mi * 16 + (l >> 2);
            const int col = bn + wn * 64 + ni * 8 + (l & 3) * 2;
            *(float2*)(C + (size_t)row * N + col)       = make_float2(acc[mi][ni][0], acc[mi][ni][1]);
            *(float2*)(C + (size_t)(row + 8) * N + col) = make_float2(acc[mi][ni][2], acc[mi][ni][3]);
        }
}

// ---------------- split helpers ----------------
__global__ void split_act(const float* __restrict__ in, bf16* __restrict__ hi,
                          bf16* __restrict__ lo) {
    size_t idx = (size_t)blockIdx.x * 256 + threadIdx.x;
    float v = in[idx];
    bf16 h = __float2bfloat16(v);
    hi[idx] = h;
    lo[idx] = __float2bfloat16(v - __bfloat162float(h));
}

// W [K][N] fp32 -> T_hi/T_lo [N][K] bf16
__global__ void transsplit(const float* __restrict__ W, bf16* __restrict__ Th,
                           bf16* __restrict__ Tl, int K, int N) {
    __shared__ float tile[32][33];
    const int k0 = blockIdx.y * 32, n0 = blockIdx.x * 32;
    const int tx = threadIdx.x & 31, ty = threadIdx.x >> 5;  // ty 0..7
#pragma unroll
    for (int i = 0; i < 32; i += 8)
        tile[ty + i][tx] = W[(size_t)(k0 + ty + i) * N + n0 + tx];
    __syncthreads();
#pragma unroll
    for (int i = 0; i < 32; i += 8) {
        float v = tile[tx][ty + i];
        bf16 h = __float2bfloat16(v);
        size_t o = (size_t)(n0 + ty + i) * K + k0 + tx;
        Th[o] = h;
        Tl[o] = __float2bfloat16(v - __bfloat162float(h));
    }
}

// ---------------- fused small projections: beta(sigmoid), fa, ga --------------
// NOTE: sx row stride must be a multiple of 4 floats (16 B) because the loader
// does float4 stores at &sx[r][cc]. 33 was misaligned for odd r; 36 is aligned.
__global__ __launch_bounds__(256)
void small_fused(const float* __restrict__ x, const float* __restrict__ Wb,
                 const float* __restrict__ Wfa, const float* __restrict__ Wga,
                 float* __restrict__ beta, float* __restrict__ fa,
                 float* __restrict__ ga) {
    __shared__ __align__(16) float sx[32][36];
    __shared__ float sW[32][160];
    const int tid = threadIdx.x;
    const int m0 = blockIdx.x * 32;
    const int rg = tid >> 4;       // rows rg, rg+16
    const int c = tid & 15;        // cols c + j*16
    float acc[2][10];
#pragma unroll
    for (int a = 0; a < 2; a++)
#pragma unroll
        for (int j = 0; j < 10; j++) acc[a][j] = 0.f;

    for (int k0 = 0; k0 < HIDN; k0 += 32) {
        {
            int r = tid >> 3, cc = (tid & 7) * 4;
            *(float4*)(&sx[r][cc]) = *(const float4*)(x + (size_t)(m0 + r) * HIDN + k0 + cc);
        }
        for (int i = tid; i < 32 * 160; i += 256) {
            int kk = i / 160, cc = i - kk * 160;
            float v;
            if (cc < 32)       v = Wb[(size_t)(k0 + kk) * HH + cc];
            else if (cc < 96)  v = Wfa[(size_t)(k0 + kk) * DD + cc - 32];
            else               v = Wga[(size_t)(k0 + kk) * DD + cc - 96];
            sW[kk][cc] = v;
        }
        __syncthreads();
#pragma unroll 4
        for (int kk = 0; kk < 32; kk++) {
            float x0 = sx[rg][kk], x1 = sx[rg + 16][kk];
#pragma unroll
            for (int j = 0; j < 10; j++) {
                float wv = sW[kk][c + j * 16];
                acc[0][j] += x0 * wv;
                acc[1][j] += x1 * wv;
            }
        }
        __syncthreads();
    }
#pragma unroll
    for (int a = 0; a < 2; a++) {
        const int m = m0 + rg + a * 16;
#pragma unroll
        for (int j = 0; j < 10; j++) {
            int co = c + j * 16;
            if (co < 32)       beta[(size_t)m * HH + co] = 1.f / (1.f + expf(-acc[a][j]));
            else if (co < 96)  fa[(size_t)m * DD + co - 32] = acc[a][j];
            else               ga[(size_t)m * DD + co - 96] = acc[a][j];
        }
    }
}

// ---------------- fp32 GEMM for the K=64 gate projections ----------------------
__global__ __launch_bounds__(256, 2)
void gemm128(const float* __restrict__ A, const float* __restrict__ B,
             float* __restrict__ C, int M, int N, int K) {
    __shared__ __align__(16) float As[16][128];
    __shared__ __align__(16) float Bs[16][128];
    const int tid = threadIdx.x;
    const int bm = blockIdx.y * 128;
    const int bn = blockIdx.x * 128;
    const int aRow = tid >> 2;
    const int aCol = (tid & 3) << 2;
    const int bRow = tid >> 5;
    const int bCol = (tid & 31) << 2;
    const int ty = (tid >> 4) << 3;
    const int tx = (tid & 15) << 3;
    float acc[8][8];
#pragma unroll
    for (int i = 0; i < 8; i++)
#pragma unroll
        for (int j = 0; j < 8; j++) acc[i][j] = 0.f;

    for (int k0 = 0; k0 < K; k0 += 16) {
        float4 a0 = *(const float4*)(A + (size_t)(bm + aRow) * K + k0 + aCol);
        float4 a1 = *(const float4*)(A + (size_t)(bm + aRow + 64) * K + k0 + aCol);
        float4 b0 = *(const float4*)(B + (size_t)(k0 + bRow) * N + bn + bCol);
        float4 b1 = *(const float4*)(B + (size_t)(k0 + bRow + 8) * N + bn + bCol);
        As[aCol + 0][aRow] = a0.x; As[aCol + 1][aRow] = a0.y;
        As[aCol + 2][aRow] = a0.z; As[aCol + 3][aRow] = a0.w;
        As[aCol + 0][aRow + 64] = a1.x; As[aCol + 1][aRow + 64] = a1.y;
        As[aCol + 2][aRow + 64] = a1.z; As[aCol + 3][aRow + 64] = a1.w;
        *(float4*)(&Bs[bRow][bCol]) = b0;
        *(float4*)(&Bs[bRow + 8][bCol]) = b1;
        __syncthreads();
#pragma unroll
        for (int kk = 0; kk < 16; kk++) {
            float ra[8], rb[8];
            *(float4*)(ra)     = *(const float4*)(&As[kk][ty]);
            *(float4*)(ra + 4) = *(const float4*)(&As[kk][ty + 4]);
            *(float4*)(rb)     = *(const float4*)(&Bs[kk][tx]);
            *(float4*)(rb + 4) = *(const float4*)(&Bs[kk][tx + 4]);
#pragma unroll
            for (int i = 0; i < 8; i++)
#pragma unroll
                for (int j = 0; j < 8; j++)
                    acc[i][j] += ra[i] * rb[j];
        }
        __syncthreads();
    }
#pragma unroll
    for (int i = 0; i < 8; i++) {
        float4* crow = (float4*)(C + (size_t)(bm + ty + i) * N + bn + tx);
        crow[0] = make_float4(acc[i][0], acc[i][1], acc[i][2], acc[i][3]);
        crow[1] = make_float4(acc[i][4], acc[i][5], acc[i][6], acc[i][7]);
    }
}

// ---------------- conv+SiLU (+ fused L2 norm for q/k) --------------------------
__global__ void conv_silu(const float* __restrict__ in, const float* __restrict__ w,
                          float* __restrict__ out) {
    int idx = blockIdx.x * 256 + threadIdx.x;
    int t = idx >> 11;
    int p = idx & (PP - 1);
    float4 wv = *(const float4*)(w + p * 4);
    float acc = in[idx] * wv.w;
    if (t >= 1) acc += in[idx - PP] * wv.z;
    if (t >= 2) acc += in[idx - 2 * PP] * wv.y;
    if (t >= 3) acc += in[idx - 3 * PP] * wv.x;
    out[idx] = acc / (1.f + expf(-acc));
}

__global__ __launch_bounds__(256)
void conv_silu_l2(const float* __restrict__ in, const float* __restrict__ w,
                  float* __restrict__ out, float scale) {
    const int row = blockIdx.x * 8 + (threadIdx.x >> 5);  // t*HH + h
    const int lane = threadIdx.x & 31;
    const int t = row >> 5, h = row & 31;
    const int p = h * 64 + lane * 2;
    const size_t idx = (size_t)t * PP + p;
    float4 w0 = *(const float4*)(w + p * 4);
    float4 w1 = *(const float4*)(w + (p + 1) * 4);
    float2 x0 = *(const float2*)(in + idx);
    float a0 = x0.x * w0.w, a1 = x0.y * w1.w;
    if (t >= 1) { float2 xm = *(const float2*)(in + idx - PP);     a0 += xm.x * w0.z; a1 += xm.y * w1.z; }
    if (t >= 2) { float2 xm = *(const float2*)(in + idx - 2 * PP); a0 += xm.x * w0.y; a1 += xm.y * w1.y; }
    if (t >= 3) { float2 xm = *(const float2*)(in + idx - 3 * PP); a0 += xm.x * w0.x; a1 += xm.y * w1.x; }
    a0 = a0 / (1.f + expf(-a0));
    a1 = a1 / (1.f + expf(-a1));
    float ss = a0 * a0 + a1 * a1;
#pragma unroll
    for (int m = 16; m; m >>= 1) ss += __shfl_xor_sync(0xffffffffu, ss, m);
    float rn = rsqrtf(ss + 1e-6f) * scale;
    *(float2*)(out + idx) = make_float2(a0 * rn, a1 * rn);
}

// ---------------- forget gate ----------------
__global__ void gate_kernel(float* __restrict__ g, const float* __restrict__ dt_bias,
                            const float* __restrict__ A_log) {
    int idx = blockIdx.x * 256 + threadIdx.x;
    int p = idx & (PP - 1);
    int h = p >> 6;
    float val = g[idx] + dt_bias[p];
    float sp = (val > 20.f) ? val : log1pf(expf(val));
    g[idx] = -expf(A_log[h]) * sp;
}

// ---------------- KDA scan ----------------
__global__ __launch_bounds__(256)
void scan_kernel(const float* __restrict__ q, const float* __restrict__ k,
                 const float* __restrict__ v, const float* __restrict__ g,
                 const float* __restrict__ beta, float* __restrict__ o) {
    const int h = blockIdx.x;
    const int cg = blockIdx.y;
    const int tid = threadIdx.x;
    const int dvl = tid >> 4;
    const int kp = tid & 15;
    const int dk0 = kp << 2;
    const int dv = (cg << 4) + dvl;

    float S0 = 0.f, S1 = 0.f, S2 = 0.f, S3 = 0.f;
    __shared__ __align__(16) float sk[64];
    __shared__ __align__(16) float sq[64];
    __shared__ __align__(16) float seg[64];
    __shared__ float sv[16];
    __shared__ float sbeta;

    for (int t = 0; t < TT; t++) {
        const int base = (t * HH + h) * DD;
        if (tid < 64) {
            sk[tid] = k[base + tid];
            sq[tid] = q[base + tid];
            seg[tid] = expf(g[base + tid]);
        } else if (tid < 80) {
            sv[tid - 64] = v[base + (cg << 4) + (tid - 64)];
        } else if (tid == 80) {
            sbeta = beta[t * HH + h];
        }
        __syncthreads();
        float4 kv = *(const float4*)(sk + dk0);
        float4 ev = *(const float4*)(seg + dk0);
        S0 *= ev.x; S1 *= ev.y; S2 *= ev.z; S3 *= ev.w;
        float vp = kv.x * S0 + kv.y * S1 + kv.z * S2 + kv.w * S3;
        vp += __shfl_xor_sync(0xffffffffu, vp, 1);
        vp += __shfl_xor_sync(0xffffffffu, vp, 2);
        vp += __shfl_xor_sync(0xffffffffu, vp, 4);
        vp += __shfl_xor_sync(0xffffffffu, vp, 8);
        const float delta = (sv[dvl] - vp) * sbeta;
        S0 += kv.x * delta; S1 += kv.y * delta;
        S2 += kv.z * delta; S3 += kv.w * delta;
        float4 qv = *(const float4*)(sq + dk0);
        float op = qv.x * S0 + qv.y * S1 + qv.z * S2 + qv.w * S3;
        op += __shfl_xor_sync(0xffffffffu, op, 1);
        op += __shfl_xor_sync(0xffffffffu, op, 2);
        op += __shfl_xor_sync(0xffffffffu, op, 4);
        op += __shfl_xor_sync(0xffffffffu, op, 8);
        if (kp == 0) o[base + dv] = op;
        __syncthreads();
    }
}

// ---------------- gated RMSNorm ----------------
__global__ void rmsnorm_gate(float* __restrict__ o, const float* __restrict__ g2,
                             const float* __restrict__ w) {
    int r = blockIdx.x * 8 + (threadIdx.x >> 5);
    int lane = threadIdx.x & 31;
    size_t base = (size_t)r * 64 + lane * 2;
    float2 ov = *(float2*)(o + base);
    float ss = ov.x * ov.x + ov.y * ov.y;
#pragma unroll
    for (int m = 16; m; m >>= 1) ss += __shfl_xor_sync(0xffffffffu, ss, m);
    float rms = rsqrtf(ss * (1.f / 64.f) + 1e-5f);
    float2 gv = *(const float2*)(g2 + base);
    float w0 = w[lane * 2], w1 = w[lane * 2 + 1];
    ov.x = ov.x * rms * w0 / (1.f + expf(-gv.x));
    ov.y = ov.y * rms * w1 / (1.f + expf(-gv.y));
    *(float2*)(o + base) = ov;
}

// ---------------- launch ----------------
extern "C" void kernel_launch(void* const* d_in, const int* in_sizes, int n_in,
                              void* d_out, int out_size) {
    (void)in_sizes; (void)n_in; (void)out_size;
    const float* x       = (const float*)d_in[0];
    const float* Wq      = (const float*)d_in[1];
    const float* Wk      = (const float*)d_in[2];
    const float* Wv      = (const float*)d_in[3];
    const float* Wb      = (const float*)d_in[4];
    const float* Wfa     = (const float*)d_in[5];
    const float* Wfb     = (const float*)d_in[6];
    const float* dt_bias = (const float*)d_in[7];
    const float* A_log   = (const float*)d_in[8];
    const float* Wga     = (const float*)d_in[9];
    const float* Wgb     = (const float*)d_in[10];
    const float* conv_q  = (const float*)d_in[11];
    const float* conv_k  = (const float*)d_in[12];
    const float* conv_v  = (const float*)d_in[13];
    const float* o_w     = (const float*)d_in[14];
    const float* Wo      = (const float*)d_in[15];
    float* out = (float*)d_out;

    float *qpre, *kpre, *vpre, *qn, *kn, *vn, *g, *g2, *ob, *beta, *fa, *ga;
    bf16 *xh, *xl, *wqth, *wqtl, *wkth, *wktl, *wvth, *wvtl, *woth, *wotl, *obh, *obl;
    cudaGetSymbolAddress((void**)&qpre, d_qpre);
    cudaGetSymbolAddress((void**)&kpre, d_kpre);
    cudaGetSymbolAddress((void**)&vpre, d_vpre);
    cudaGetSymbolAddress((void**)&qn, d_qn);
    cudaGetSymbolAddress((void**)&kn, d_kn);
    cudaGetSymbolAddress((void**)&vn, d_vn);
    cudaGetSymbolAddress((void**)&g, d_g);
    cudaGetSymbolAddress((void**)&g2, d_g2);
    cudaGetSymbolAddress((void**)&ob, d_ob);
    cudaGetSymbolAddress((void**)&beta, d_beta);
    cudaGetSymbolAddress((void**)&fa, d_fa);
    cudaGetSymbolAddress((void**)&ga, d_ga);
    cudaGetSymbolAddress((void**)&xh, d_xh);
    cudaGetSymbolAddress((void**)&xl, d_xl);
    cudaGetSymbolAddress((void**)&wqth, d_wqth);
    cudaGetSymbolAddress((void**)&wqtl, d_wqtl);
    cudaGetSymbolAddress((void**)&wkth, d_wkth);
    cudaGetSymbolAddress((void**)&wktl, d_wktl);
    cudaGetSymbolAddress((void**)&wvth, d_wvth);
    cudaGetSymbolAddress((void**)&wvtl, d_wvtl);
    cudaGetSymbolAddress((void**)&woth, d_woth);
    cudaGetSymbolAddress((void**)&wotl, d_wotl);
    cudaGetSymbolAddress((void**)&obh, d_obh);
    cudaGetSymbolAddress((void**)&obl, d_obl);

    // ---- prep: split activations, transpose+split weights ----
    split_act<<<(TT * HIDN) / 256, 256>>>(x, xh, xl);
    transsplit<<<dim3(PP / 32, HIDN / 32), 256>>>(Wq, wqth, wqtl, HIDN, PP);
    transsplit<<<dim3(PP / 32, HIDN / 32), 256>>>(Wk, wkth, wktl, HIDN, PP);
    transsplit<<<dim3(PP / 32, HIDN / 32), 256>>>(Wv, wvth, wvtl, HIDN, PP);
    transsplit<<<dim3(HIDN / 32, PP / 32), 256>>>(Wo, woth, wotl, PP, HIDN);

    // ---- big GEMMs on tensor cores ----
    dim3 gQKV(PP / 128, TT / 128);
    gemm_tc<<<gQKV, 256>>>(xh, xl, wqth, wqtl, qpre, TT, PP, HIDN);
    gemm_tc<<<gQKV, 256>>>(xh, xl, wkth, wktl, kpre, TT, PP, HIDN);
    gemm_tc<<<gQKV, 256>>>(xh, xl, wvth, wvtl, vpre, TT, PP, HIDN);

    // ---- small projections (fused) + gate projections ----
    small_fused<<<TT / 32, 256>>>(x, Wb, Wfa, Wga, beta, fa, ga);
    gemm128<<<gQKV, 256>>>(fa, Wfb, g,  TT, PP, DD);
    gemm128<<<gQKV, 256>>>(ga, Wgb, g2, TT, PP, DD);

    // ---- conv + SiLU (+ L2 norm for q/k) ----
    conv_silu_l2<<<TT * HH / 8, 256>>>(qpre, conv_q, qn, 0.125f);
    conv_silu_l2<<<TT * HH / 8, 256>>>(kpre, conv_k, kn, 1.0f);
    conv_silu<<<TT * PP / 256, 256>>>(vpre, conv_v, vn);

    // ---- forget gate ----
    gate_kernel<<<TT * PP / 256, 256>>>(g, dt_bias, A_log);

    // ---- recurrent scan ----
    scan_kernel<<<dim3(HH, 4), 256>>>(qn, kn, vn, g, beta, ob);

    // ---- gated RMSNorm ----
    rmsnorm_gate<<<TT * HH / 8, 256>>>(ob, g2, o_w);

    // ---- output projection on tensor cores ----
    split_act<<<(TT * PP) / 256, 256>>>(ob, obh, obl);
    gemm_tc<<<dim3(HIDN / 128, TT / 128), 256>>>(obh, obl, woth, wotl, out, TT, HIDN, PP);
}